// round 14
// baseline (speedup 1.0000x reference)
#include <cuda_runtime.h>
#include <math.h>

#define BATCH    8
#define NCLS     80
#define NTOT     76725
#define CAND_TOT 4125
#define TOPN     1000
#define MAXDET   100
#define NEGV     (-1e9f)
#define MIN_SC   0.05f

// level geometry
#define N0 57600
#define N1 14400
#define N2 3600
#define N3 900
#define N4 225
#define O1 57600
#define O2 72000
#define O3 75600
#define O4 76500
#define C1 1000
#define C2 2000
#define C3 3000
#define C4 3900

#define NBC ((BATCH * NTOT + 255) / 256)   // compact blocks

// libdevice accurate expf — immune to --use_fast_math rewriting of expf->__expf.
extern "C" __device__ float __nv_expf(float);

// ---------------- scratch (device globals: no allocation allowed) ----------------
__device__ float              g_scores[BATCH * NTOT];
__device__ unsigned char      g_cls  [BATCH * NTOT];
__device__ unsigned int       g_thr [BATCH * 3];
__device__ int                g_cgt [BATCH * 3];
__device__ int                g_cnt [BATCH * 3];
__device__ float              g_cscore[BATCH * CAND_TOT];
__device__ unsigned int       g_cmeta [BATCH * CAND_TOT]; // (cls<<24)|(level<<16)|orig_idx
__device__ unsigned long long g_ckey  [BATCH * CAND_TOT]; // fkey<<24 | inv(meta low 24) — unique
__device__ float4             g_cbox  [BATCH * CAND_TOT];

__device__ __forceinline__ unsigned int fkey(float f) {
    unsigned int u = __float_as_uint(f);
    return (u & 0x80000000u) ? ~u : (u | 0x80000000u);
}

// Box decode, bit-matching reference op order (no fma contraction; exact libdevice exp)
__device__ __forceinline__ float4 decode_box(const float4 rg, const float4 an) {
    float ww  = __fsub_rn(an.z, an.x);
    float hh  = __fsub_rn(an.w, an.y);
    float cx  = __fadd_rn(an.x, __fmul_rn(0.5f, ww));
    float cy  = __fadd_rn(an.y, __fmul_rn(0.5f, hh));
    float rx  = __fmul_rn(rg.x, 0.1f);
    float ry  = __fmul_rn(rg.y, 0.1f);
    float rw  = __fmul_rn(rg.z, 0.2f);
    float rh  = __fmul_rn(rg.w, 0.2f);
    float pw  = __fmul_rn(__nv_expf(rw), ww);
    float ph  = __fmul_rn(__nv_expf(rh), hh);
    float pcx = __fadd_rn(__fmul_rn(rx, ww), cx);
    float pcy = __fadd_rn(__fmul_rn(ry, hh), cy);
    int x1 = (int)__fsub_rn(pcx, __fmul_rn(0.5f, pw));
    int y1 = (int)__fsub_rn(pcy, __fmul_rn(0.5f, ph));
    int x2 = (int)__fadd_rn(pcx, __fmul_rn(0.5f, pw));
    int y2 = (int)__fadd_rn(pcy, __fmul_rn(0.5f, ph));
    x1 = max(x1, 0); y1 = max(y1, 0);
    x2 = min(x2, 639); y2 = min(y2, 639);
    return make_float4((float)x1, (float)y1, (float)x2, (float)y2);
}

__device__ __forceinline__ void level_of(int jj, int& l, int& j, int& n) {
    if (jj < O1)      { l = 0; j = jj;      n = N0; }
    else if (jj < O2) { l = 1; j = jj - O1; n = N1; }
    else if (jj < O3) { l = 2; j = jj - O2; n = N2; }
    else if (jj < O4) { l = 3; j = jj - O3; n = N3; }
    else              { l = 4; j = jj - O4; n = N4; }
}

// ---------------- Kernel A: coalesced max/argmax, 4 lanes per anchor ----------------
// Exit boundary 4*BATCH*NTOT is a multiple of 32 -> warp-aligned exits, shfl-safe.
// One warp covers 8 anchors = 2560 contiguous bytes, zero overfetch per LDG.128.
__global__ void score_kernel(const float* __restrict__ c0, const float* __restrict__ c1,
                             const float* __restrict__ c2, const float* __restrict__ c3,
                             const float* __restrict__ c4) {
    int id = blockIdx.x * blockDim.x + threadIdx.x;      // over 4 * BATCH * NTOT
    int aid = id >> 2;
    int g = id & 3;                                      // class-segment 20g..20g+19
    if (aid >= BATCH * NTOT) return;
    int b = aid / NTOT, jj = aid - b * NTOT;
    int l, j, n;
    level_of(jj, l, j, n);
    const float* base = (l == 0) ? c0 : (l == 1) ? c1 : (l == 2) ? c2 : (l == 3) ? c3 : c4;
    const float4* p = (const float4*)base + ((size_t)b * n + j) * 20 + g * 5;
    float m = -1e30f; int a = 0;
#pragma unroll
    for (int i = 0; i < 5; i++) {
        float4 v = p[i];
        int cb = g * 20 + i * 4;
        if (v.x > m) { m = v.x; a = cb; }
        if (v.y > m) { m = v.y; a = cb + 1; }
        if (v.z > m) { m = v.z; a = cb + 2; }
        if (v.w > m) { m = v.w; a = cb + 3; }
    }
    // reduce across the 4 lanes of this anchor (strict > keeps earliest class: exact argmax)
#pragma unroll
    for (int off = 2; off >= 1; off >>= 1) {
        float om = __shfl_down_sync(0xFFFFFFFFu, m, off, 4);
        int   oa = __shfl_down_sync(0xFFFFFFFFu, a, off, 4);
        if (om > m) { m = om; a = oa; }
    }
    if (g == 0) {
        int o = b * NTOT + jj;
        g_scores[o] = m;
        g_cls[o] = (unsigned char)a;
    }
}

// ---------------- Kernel B: exact 1000th-largest via MSB radix select ----------------
__global__ void topk_thresh_kernel() {
    const int NL[3] = {N0, N1, N2};
    const int LO[3] = {0, O1, O2};
    int bi = blockIdx.x;
    int b = bi / 3, l = bi % 3;
    int n = NL[l];
    const float* sc = g_scores + b * NTOT + LO[l];

    __shared__ unsigned int hist[256];
    __shared__ unsigned int s_prefix;
    __shared__ int s_krem, s_cgt;
    if (threadIdx.x == 0) { s_prefix = 0; s_krem = TOPN; s_cgt = 0; g_cnt[bi] = 0; }
    __syncthreads();

    for (int round = 0; round < 4; round++) {
        int shift = 24 - 8 * round;
        for (int i = threadIdx.x; i < 256; i += blockDim.x) hist[i] = 0;
        __syncthreads();
        unsigned int prefix = s_prefix;
        unsigned int pmask = (round == 0) ? 0u : (0xFFFFFFFFu << (shift + 8));
        for (int i = threadIdx.x; i < n; i += blockDim.x) {
            unsigned int k = fkey(sc[i]);
            if ((k & pmask) == prefix) {
                unsigned int bin = (k >> shift) & 255;
                unsigned int act = __activemask();
                unsigned int mm = __match_any_sync(act, bin);
                int leader = __ffs(mm) - 1;
                if ((int)(threadIdx.x & 31) == leader)
                    atomicAdd(&hist[bin], __popc(mm));
            }
        }
        __syncthreads();
        if (threadIdx.x == 0) {
            int krem = s_krem;
            unsigned int acc = 0;
            int bin = 255;
            for (; bin > 0; bin--) {
                unsigned int c = hist[bin];
                if (acc + c >= (unsigned int)krem) break;
                acc += c;
            }
            s_prefix = prefix | ((unsigned int)bin << shift);
            s_krem = krem - (int)acc;
            s_cgt += (int)acc;
        }
        __syncthreads();
    }
    if (threadIdx.x == 0) {
        g_thr[bi] = s_prefix;
        g_cgt[bi] = s_cgt;
    }
}

// ---------------- Kernel C (fused): compact (> T) + decode, plus fixup (== T) blocks ----------------
__device__ __forceinline__ void emit_cand(int o, float s, unsigned int meta, float4 box) {
    g_cscore[o] = s;
    g_cmeta[o]  = meta;
    g_ckey[o]   = ((unsigned long long)fkey(s) << 24)
                | (unsigned long long)(0x00FFFFFFu - (meta & 0x00FFFFFFu));
    g_cbox[o]   = box;
}

__global__ void compact_fixup_kernel(
    const float* __restrict__ r0, const float* __restrict__ r1, const float* __restrict__ r2,
    const float* __restrict__ r3, const float* __restrict__ r4,
    const float* __restrict__ a0, const float* __restrict__ a1, const float* __restrict__ a2,
    const float* __restrict__ a3, const float* __restrict__ a4) {

    __shared__ int list[512];
    __shared__ int cnt;

    if (blockIdx.x < NBC) {
        int id = blockIdx.x * blockDim.x + threadIdx.x;
        if (id >= BATCH * NTOT) return;
        int b = id / NTOT, jj = id - b * NTOT;
        int l, j, n;
        level_of(jj, l, j, n);
        float s = g_scores[b * NTOT + jj];
        int slot;
        if (l < 3) {
            if (fkey(s) <= g_thr[b * 3 + l]) return;
            int p = atomicAdd(&g_cnt[b * 3 + l], 1);
            if (p >= TOPN) return;
            slot = ((l == 0) ? 0 : (l == 1) ? C1 : C2) + p;
        } else {
            slot = ((l == 3) ? C3 : C4) + j;
        }
        const float* regp = (l == 0) ? r0 : (l == 1) ? r1 : (l == 2) ? r2 : (l == 3) ? r3 : r4;
        const float* ancp = (l == 0) ? a0 : (l == 1) ? a1 : (l == 2) ? a2 : (l == 3) ? a3 : a4;
        float4 rg = ((const float4*)regp)[(size_t)b * n + j];
        float4 an = ((const float4*)ancp)[(size_t)b * n + j];
        unsigned int meta = ((unsigned int)g_cls[b * NTOT + jj] << 24)
                          | ((unsigned int)l << 16) | (unsigned int)j;
        emit_cand(b * CAND_TOT + slot, s, meta, decode_box(rg, an));
    } else {
        const int NL[3] = {N0, N1, N2};
        const int LO[3] = {0, O1, O2};
        const int CB[3] = {0, C1, C2};
        int bi = blockIdx.x - NBC;          // 0..23
        int b = bi / 3, l = bi % 3;
        unsigned int T = g_thr[bi];
        int cgt = g_cgt[bi];
        int jt = TOPN - cgt;                // >= 1
        int n = NL[l];
        const float* sc = g_scores + b * NTOT + LO[l];

        if (threadIdx.x == 0) cnt = 0;
        __syncthreads();
        for (int i = threadIdx.x; i < n; i += blockDim.x) {
            if (fkey(sc[i]) == T) {
                int p = atomicAdd(&cnt, 1);
                if (p < 512) list[p] = i;
            }
        }
        __syncthreads();
        int m = min(cnt, 512);
        if (threadIdx.x == 0) {
            for (int i = 1; i < m; i++) {
                int v = list[i]; int k = i - 1;
                while (k >= 0 && list[k] > v) { list[k + 1] = list[k]; k--; }
                list[k + 1] = v;
            }
        }
        __syncthreads();
        const float* regp = (l == 0) ? r0 : ((l == 1) ? r1 : r2);
        const float* ancp = (l == 0) ? a0 : ((l == 1) ? a1 : a2);
        for (int i = threadIdx.x; i < jt; i += blockDim.x) {
            int o = b * CAND_TOT + CB[l] + cgt + i;
            if (i < m) {
                int j = list[i];
                float4 rg = ((const float4*)regp)[(size_t)b * n + j];
                float4 an = ((const float4*)ancp)[(size_t)b * n + j];
                unsigned int meta = ((unsigned int)g_cls[b * NTOT + LO[l] + j] << 24)
                                  | ((unsigned int)l << 16) | (unsigned int)j;
                emit_cand(o, sc[j], meta, decode_box(rg, an));
            } else {
                emit_cand(o, NEGV, (7u << 16) | (unsigned int)i, make_float4(0.f, 0.f, 0.f, 0.f));
            }
        }
    }
}

// ---------------- Kernel D: sorted-tranche greedy NMS ----------------
// Per batch block: radix-select top-512 unprocessed keys, rank them in-block,
// build pairwise suppression rows, warp-serial resolve. Exact greedy equivalence
// to iterative argmax (keys unique; tie-break = earliest concat position).
#define TR 512
struct SmemNMS {
    union {
        struct {
            unsigned long long tk[TR];   // tranche keys (gather order)
            int                tc[TR];   // tranche candidate slots
        } ph1;
        unsigned int row[TR][16];        // row[i] bit j: "i suppresses j" (sorted idx)
    } u;                                 // 32 KB
    float4        sbox[TR];              // sorted boxes        8 KB
    float         sscore[TR];            // sorted scores       2 KB
    unsigned char scls[TR];              // sorted classes      0.5 KB
    float4        abox[MAXDET];          // accepted boxes      1.6 KB
    float         aarea[MAXDET];         // accepted areas      0.4 KB
    unsigned int  hist[256];             //                     1 KB
    unsigned int  aw[16];                // alive words
    unsigned long long prefix;
    unsigned long long Tlow;             // exclusive upper bound of next tranche
    int krem, tcnt, na, processed;
};

__device__ __forceinline__ int supp_test(float4 A, float aA, float4 B, float aB) {
    float tlx = fmaxf(A.x, B.x), tly = fmaxf(A.y, B.y);
    float brx = fminf(A.z, B.z), bry = fminf(A.w, B.w);
    float w = fmaxf(brx - tlx, 0.f), h = fmaxf(bry - tly, 0.f);
    float inter = w * h;
    // exact integer equivalence of inter/max(union,1e-4) >= 0.5 (inter>0 guards clamp path)
    return (inter > 0.f) && (3.0f * inter >= aA + aB);
}

__global__ __launch_bounds__(TR, 1) void nms_kernel(float* __restrict__ out) {
    __shared__ SmemNMS sm;
    int b = blockIdx.x;
    int t = threadIdx.x;
    int lane = t & 31, warp = t >> 5;
    const unsigned long long* keys = g_ckey + b * CAND_TOT;

    float* outS = out + b * MAXDET;
    float* outC = out + BATCH * MAXDET + b * MAXDET;
    float* outB = out + 2 * BATCH * MAXDET + (size_t)b * MAXDET * 4;

    if (t == 0) { sm.na = 0; sm.processed = 0; sm.Tlow = 0xFFFFFFFFFFFFFFFFull; }
    __syncthreads();

    for (int tranche = 0; tranche < (CAND_TOT + TR - 1) / TR; tranche++) {
        if (sm.na >= MAXDET || sm.processed >= CAND_TOT) break;   // uniform (post-barrier)
        int rem = CAND_TOT - sm.processed;
        unsigned long long Thi = sm.Tlow;
        unsigned long long T = 0;

        if (rem > TR) {
            // radix-select the TR-th largest key among {key < Thi} (keys unique, 56 bits)
            if (t == 0) { sm.prefix = 0; sm.krem = TR; }
            __syncthreads();
            for (int round = 0; round < 7; round++) {
                int shift = 48 - 8 * round;
                if (t < 256) sm.hist[t] = 0;
                __syncthreads();
                unsigned long long pref = sm.prefix;
                unsigned long long hm = (round == 0) ? 0ull : (0xFFFFFFFFFFFFFFFFull << (shift + 8));
                for (int i = t; i < CAND_TOT; i += TR) {
                    unsigned long long kk = keys[i];
                    if (kk < Thi && (kk & hm) == pref) {
                        unsigned int bin = (unsigned int)(kk >> shift) & 255u;
                        unsigned int act = __activemask();
                        unsigned int mm = __match_any_sync(act, bin);
                        int leader = __ffs(mm) - 1;
                        if (lane == leader) atomicAdd(&sm.hist[bin], __popc(mm));
                    }
                }
                __syncthreads();
                if (t == 0) {
                    int kr = sm.krem;
                    unsigned int acc = 0;
                    int bin = 255;
                    for (; bin > 0; bin--) {
                        unsigned int c = sm.hist[bin];
                        if (acc + c >= (unsigned int)kr) break;
                        acc += c;
                    }
                    sm.prefix = pref | ((unsigned long long)bin << shift);
                    sm.krem = kr - (int)acc;
                }
                __syncthreads();
            }
            T = sm.prefix;   // exact TR-th largest key below Thi
        }

        // gather tranche: keys in [T, Thi)
        if (t == 0) sm.tcnt = 0;
        __syncthreads();
        for (int i = t; i < CAND_TOT; i += TR) {
            unsigned long long kk = keys[i];
            if (kk >= T && kk < Thi) {
                int p = atomicAdd(&sm.tcnt, 1);
                if (p < TR) { sm.u.ph1.tk[p] = kk; sm.u.ph1.tc[p] = i; }
            }
        }
        __syncthreads();
        int kc = min(sm.tcnt, TR);

        // rank within tranche (descending, unique keys -> exact permutation)
        int r = -1; float4 mybox; float mysc = 0.f; unsigned int mycls = 0;
        if (t < kc) {
            unsigned long long myk = sm.u.ph1.tk[t];
            int myc = sm.u.ph1.tc[t];
            int rr = 0;
            for (int j2 = 0; j2 < kc; j2++) rr += (sm.u.ph1.tk[j2] > myk) ? 1 : 0;
            r = rr;
            mybox = g_cbox[b * CAND_TOT + myc];
            mysc  = g_cscore[b * CAND_TOT + myc];
            mycls = g_cmeta[b * CAND_TOT + myc] >> 24;
        }
        __syncthreads();   // tk/tc reads done before union overwritten
        if (t < kc) {
            sm.sbox[r] = mybox;
            sm.sscore[r] = mysc;
            sm.scls[r] = (unsigned char)mycls;
        }
        if (t == 0) { sm.processed += kc; sm.Tlow = (rem > TR) ? T : 0ull; }
        __syncthreads();

        if (!(sm.sscore[0] > MIN_SC)) break;   // all remaining invalid (sorted desc) — uniform

        // per-thread sorted candidate at position t
        int na0 = sm.na;
        float4 bx; float ar = 0.f;
        int dead = 1;
        if (t < kc) {
            bx = sm.sbox[t];
            ar = (bx.z - bx.x) * (bx.w - bx.y);
            dead = !(sm.sscore[t] > MIN_SC);
            if (!dead) {
                for (int a2 = 0; a2 < na0; a2++)
                    if (supp_test(bx, ar, sm.abox[a2], sm.aarea[a2])) { dead = 1; break; }
            }
        }
        // build suppression row over later sorted candidates
        unsigned int rowp[16];
#pragma unroll
        for (int w = 0; w < 16; w++) rowp[w] = 0;
        if (!dead) {
            for (int j2 = t + 1; j2 < kc; j2++) {
                float4 bj = sm.sbox[j2];
                float aj = (bj.z - bj.x) * (bj.w - bj.y);
                if (supp_test(bx, ar, bj, aj)) rowp[j2 >> 5] |= (1u << (j2 & 31));
            }
        }
#pragma unroll
        for (int w = 0; w < 16; w++) sm.u.row[t][w] = rowp[w];
        unsigned int bal = __ballot_sync(0xFFFFFFFFu, !dead);
        if (lane == 0) sm.aw[warp] = bal;
        __syncthreads();

        // resolve: warp 0, lane w owns alive word w
        if (warp == 0) {
            unsigned int aw = (lane < 16) ? sm.aw[lane] : 0u;
            int na = sm.na;
            while (na < MAXDET) {
                unsigned int anyb = __ballot_sync(0xFFFFFFFFu, aw != 0u) & 0xFFFFu;
                if (!anyb) break;
                int w = __ffs(anyb) - 1;
                unsigned int word = __shfl_sync(0xFFFFFFFFu, aw, w);
                int bit = __ffs(word) - 1;
                int pos = w * 32 + bit;
                if (lane == 0) {
                    float4 bb = sm.sbox[pos];
                    outS[na] = sm.sscore[pos];
                    outC[na] = (float)sm.scls[pos];
                    ((float4*)outB)[na] = bb;
                    sm.abox[na] = bb;
                    sm.aarea[na] = (bb.z - bb.x) * (bb.w - bb.y);
                }
                if (lane < 16) aw &= ~sm.u.row[pos][lane];
                if (lane == w) aw &= ~(1u << bit);
                na++;
            }
            if (lane == 0) sm.na = na;
        }
        __syncthreads();
    }

    __syncthreads();
    int na = sm.na;
    for (int d = na + t; d < MAXDET; d += TR) {
        outS[d] = -1.0f;
        outC[d] = -1.0f;
        ((float4*)outB)[d] = make_float4(-1.f, -1.f, -1.f, -1.f);
    }
}

// ---------------- launch ----------------
extern "C" void kernel_launch(void* const* d_in, const int* in_sizes, int n_in,
                              void* d_out, int out_size) {
    (void)n_in; (void)out_size;

    // Autodetect input ordering (interleaved dict order vs grouped signature order)
    int interleaved = (in_sizes[1] == BATCH * N0 * 4) ? 1 : 0;
    const float* CLS[5]; const float* REG[5]; const float* ANC[5];
    for (int l = 0; l < 5; l++) {
        if (interleaved) {
            CLS[l] = (const float*)d_in[3 * l];
            REG[l] = (const float*)d_in[3 * l + 1];
            ANC[l] = (const float*)d_in[3 * l + 2];
        } else {
            CLS[l] = (const float*)d_in[l];
            REG[l] = (const float*)d_in[5 + l];
            ANC[l] = (const float*)d_in[10 + l];
        }
    }

    int t4 = BATCH * NTOT * 4;
    score_kernel<<<(t4 + 255) / 256, 256>>>(CLS[0], CLS[1], CLS[2], CLS[3], CLS[4]);
    topk_thresh_kernel<<<24, 256>>>();
    compact_fixup_kernel<<<NBC + 24, 256>>>(REG[0], REG[1], REG[2], REG[3], REG[4],
                                            ANC[0], ANC[1], ANC[2], ANC[3], ANC[4]);
    nms_kernel<<<BATCH, TR>>>((float*)d_out);
}

// round 17
// speedup vs baseline: 1.3906x; 1.3906x over previous
#include <cuda_runtime.h>
#include <math.h>

#define BATCH    8
#define NCLS     80
#define NTOT     76725
#define CAND_TOT 4125
#define TOPN     1000
#define MAXDET   100
#define NEGV     (-1e9f)
#define MIN_SC   0.05f

// level geometry
#define N0 57600
#define N1 14400
#define N2 3600
#define N3 900
#define N4 225
#define O1 57600
#define O2 72000
#define O3 75600
#define O4 76500
#define C1 1000
#define C2 2000
#define C3 3000
#define C4 3900

#define NBC ((BATCH * NTOT + 255) / 256)   // compact blocks

// libdevice accurate expf — immune to --use_fast_math rewriting of expf->__expf.
extern "C" __device__ float __nv_expf(float);

// ---------------- scratch (device globals: no allocation allowed) ----------------
__device__ float              g_scores[BATCH * NTOT];
__device__ unsigned char      g_cls  [BATCH * NTOT];
__device__ unsigned int       g_thr [BATCH * 3];
__device__ int                g_cgt [BATCH * 3];
__device__ int                g_cnt [BATCH * 3];
__device__ float              g_cscore[BATCH * CAND_TOT];
__device__ unsigned int       g_cmeta [BATCH * CAND_TOT]; // (cls<<24)|(level<<16)|orig_idx
__device__ unsigned long long g_ckey  [BATCH * CAND_TOT]; // fkey<<24 | inv(meta low 24) — unique
__device__ float4             g_cbox  [BATCH * CAND_TOT];

__device__ __forceinline__ unsigned int fkey(float f) {
    unsigned int u = __float_as_uint(f);
    return (u & 0x80000000u) ? ~u : (u | 0x80000000u);
}

// Box decode, bit-matching reference op order (no fma contraction; exact libdevice exp)
__device__ __forceinline__ float4 decode_box(const float4 rg, const float4 an) {
    float ww  = __fsub_rn(an.z, an.x);
    float hh  = __fsub_rn(an.w, an.y);
    float cx  = __fadd_rn(an.x, __fmul_rn(0.5f, ww));
    float cy  = __fadd_rn(an.y, __fmul_rn(0.5f, hh));
    float rx  = __fmul_rn(rg.x, 0.1f);
    float ry  = __fmul_rn(rg.y, 0.1f);
    float rw  = __fmul_rn(rg.z, 0.2f);
    float rh  = __fmul_rn(rg.w, 0.2f);
    float pw  = __fmul_rn(__nv_expf(rw), ww);
    float ph  = __fmul_rn(__nv_expf(rh), hh);
    float pcx = __fadd_rn(__fmul_rn(rx, ww), cx);
    float pcy = __fadd_rn(__fmul_rn(ry, hh), cy);
    int x1 = (int)__fsub_rn(pcx, __fmul_rn(0.5f, pw));
    int y1 = (int)__fsub_rn(pcy, __fmul_rn(0.5f, ph));
    int x2 = (int)__fadd_rn(pcx, __fmul_rn(0.5f, pw));
    int y2 = (int)__fadd_rn(pcy, __fmul_rn(0.5f, ph));
    x1 = max(x1, 0); y1 = max(y1, 0);
    x2 = min(x2, 639); y2 = min(y2, 639);
    return make_float4((float)x1, (float)y1, (float)x2, (float)y2);
}

__device__ __forceinline__ void level_of(int jj, int& l, int& j, int& n) {
    if (jj < O1)      { l = 0; j = jj;      n = N0; }
    else if (jj < O2) { l = 1; j = jj - O1; n = N1; }
    else if (jj < O3) { l = 2; j = jj - O2; n = N2; }
    else if (jj < O4) { l = 3; j = jj - O3; n = N3; }
    else              { l = 4; j = jj - O4; n = N4; }
}

// ---------------- Kernel A: warp-per-anchor max/argmax (dense LDG.32) ----------------
// Lane L reads classes L, L+32, L+64(<80): per instruction the warp covers one
// dense 128B span -> ~1 wavefront per line. Grid is exact (no partial warps).
__global__ void score_kernel(const float* __restrict__ c0, const float* __restrict__ c1,
                             const float* __restrict__ c2, const float* __restrict__ c3,
                             const float* __restrict__ c4) {
    int tid = blockIdx.x * blockDim.x + threadIdx.x;
    int gw = tid >> 5;                 // global warp id == anchor id (grid sized exactly)
    int lane = tid & 31;
    int b = gw / NTOT, jj = gw - b * NTOT;
    int l, j, n;
    level_of(jj, l, j, n);
    const float* base = (l == 0) ? c0 : (l == 1) ? c1 : (l == 2) ? c2 : (l == 3) ? c3 : c4;
    const float* p = base + ((size_t)b * n + j) * NCLS;

    float v0 = p[lane];
    float v1 = p[lane + 32];
    float m = v0; int a = lane;                    // ascending class order: strict > keeps earliest
    if (v1 > m) { m = v1; a = lane + 32; }
    if (lane < 16) {
        float v2 = p[lane + 64];
        if (v2 > m) { m = v2; a = lane + 64; }
    }
    // cross-lane reduce; ties -> smaller class index (exact jnp.argmax first-occurrence)
#pragma unroll
    for (int off = 16; off; off >>= 1) {
        float om = __shfl_down_sync(0xFFFFFFFFu, m, off);
        int   oa = __shfl_down_sync(0xFFFFFFFFu, a, off);
        if (om > m || (om == m && oa < a)) { m = om; a = oa; }
    }
    if (lane == 0) {
        int o = b * NTOT + jj;
        g_scores[o] = m;
        g_cls[o] = (unsigned char)a;
    }
}

// ---------------- Kernel B: exact 1000th-largest via MSB radix select ----------------
// Parallel suffix-scan bin selection (no serial thread-0 walk).
__global__ void topk_thresh_kernel() {
    const int NL[3] = {N0, N1, N2};
    const int LO[3] = {0, O1, O2};
    int bi = blockIdx.x;
    int b = bi / 3, l = bi % 3;
    int n = NL[l];
    const float* sc = g_scores + b * NTOT + LO[l];
    int t = threadIdx.x;
    int lane = t & 31, warp = t >> 5;

    __shared__ unsigned int hist[256];
    __shared__ unsigned int wsum[8];
    __shared__ unsigned int s_prefix;
    __shared__ int s_krem, s_cgt;
    if (t == 0) { s_prefix = 0; s_krem = TOPN; s_cgt = 0; g_cnt[bi] = 0; }
    __syncthreads();

    for (int round = 0; round < 4; round++) {
        int shift = 24 - 8 * round;
        unsigned int prefix = s_prefix;
        int krem = s_krem;
        hist[t] = 0;                               // blockDim == 256
        __syncthreads();
        unsigned int pmask = (round == 0) ? 0u : (0xFFFFFFFFu << (shift + 8));
        for (int i = t; i < n; i += 256) {
            unsigned int k = fkey(sc[i]);
            if ((k & pmask) == prefix) {
                unsigned int bin = (k >> shift) & 255;
                unsigned int act = __activemask();
                unsigned int mm = __match_any_sync(act, bin);
                int leader = __ffs(mm) - 1;
                if (lane == leader) atomicAdd(&hist[bin], __popc(mm));
            }
        }
        __syncthreads();
        // parallel suffix scan over 256 bins
        unsigned int val = hist[t];
        unsigned int x = val;
#pragma unroll
        for (int off = 1; off < 32; off <<= 1) {
            unsigned int y = __shfl_down_sync(0xFFFFFFFFu, x, off);
            if (lane + off < 32) x += y;
        }
        if (lane == 0) wsum[warp] = x;             // warp total (8 warps)
        __syncthreads();
        unsigned int hi = 0;
        for (int w2 = warp + 1; w2 < 8; w2++) hi += wsum[w2];
        unsigned int suf_incl = x + hi;
        unsigned int suf_excl = suf_incl - val;
        if (suf_excl < (unsigned int)krem && suf_incl >= (unsigned int)krem) {
            s_prefix = prefix | ((unsigned int)t << shift);
            s_krem = krem - (int)suf_excl;
            s_cgt += (int)suf_excl;
        }
        __syncthreads();
    }
    if (t == 0) {
        g_thr[bi] = s_prefix;
        g_cgt[bi] = s_cgt;
    }
}

// ---------------- Kernel C (fused): compact (> T) + decode, plus fixup (== T) blocks ----------------
__device__ __forceinline__ void emit_cand(int o, float s, unsigned int meta, float4 box) {
    g_cscore[o] = s;
    g_cmeta[o]  = meta;
    g_ckey[o]   = ((unsigned long long)fkey(s) << 24)
                | (unsigned long long)(0x00FFFFFFu - (meta & 0x00FFFFFFu));
    g_cbox[o]   = box;
}

__global__ void compact_fixup_kernel(
    const float* __restrict__ r0, const float* __restrict__ r1, const float* __restrict__ r2,
    const float* __restrict__ r3, const float* __restrict__ r4,
    const float* __restrict__ a0, const float* __restrict__ a1, const float* __restrict__ a2,
    const float* __restrict__ a3, const float* __restrict__ a4) {

    __shared__ int list[512];
    __shared__ int cnt;

    if (blockIdx.x < NBC) {
        int id = blockIdx.x * blockDim.x + threadIdx.x;
        if (id >= BATCH * NTOT) return;
        int b = id / NTOT, jj = id - b * NTOT;
        int l, j, n;
        level_of(jj, l, j, n);
        float s = g_scores[b * NTOT + jj];
        int slot;
        if (l < 3) {
            int bi = b * 3 + l;
            if (fkey(s) <= g_thr[bi]) return;
            // warp-aggregated slot allocation (order irrelevant: tie-break uses meta)
            int lane = threadIdx.x & 31;
            unsigned int act = __activemask();
            unsigned int mm = __match_any_sync(act, bi);
            int leader = __ffs(mm) - 1;
            int base;
            if (lane == leader) base = atomicAdd(&g_cnt[bi], __popc(mm));
            base = __shfl_sync(mm, base, leader);
            int p = base + __popc(mm & ((1u << lane) - 1));
            if (p >= TOPN) return;                 // safety (can't happen: exact radix select)
            slot = ((l == 0) ? 0 : (l == 1) ? C1 : C2) + p;
        } else {
            slot = ((l == 3) ? C3 : C4) + j;
        }
        const float* regp = (l == 0) ? r0 : (l == 1) ? r1 : (l == 2) ? r2 : (l == 3) ? r3 : r4;
        const float* ancp = (l == 0) ? a0 : (l == 1) ? a1 : (l == 2) ? a2 : (l == 3) ? a3 : a4;
        float4 rg = ((const float4*)regp)[(size_t)b * n + j];
        float4 an = ((const float4*)ancp)[(size_t)b * n + j];
        unsigned int meta = ((unsigned int)g_cls[b * NTOT + jj] << 24)
                          | ((unsigned int)l << 16) | (unsigned int)j;
        emit_cand(b * CAND_TOT + slot, s, meta, decode_box(rg, an));
    } else {
        const int NL[3] = {N0, N1, N2};
        const int LO[3] = {0, O1, O2};
        const int CB[3] = {0, C1, C2};
        int bi = blockIdx.x - NBC;          // 0..23
        int b = bi / 3, l = bi % 3;
        unsigned int T = g_thr[bi];
        int cgt = g_cgt[bi];
        int jt = TOPN - cgt;                // >= 1
        int n = NL[l];
        const float* sc = g_scores + b * NTOT + LO[l];

        if (threadIdx.x == 0) cnt = 0;
        __syncthreads();
        for (int i = threadIdx.x; i < n; i += blockDim.x) {
            if (fkey(sc[i]) == T) {
                int p = atomicAdd(&cnt, 1);
                if (p < 512) list[p] = i;
            }
        }
        __syncthreads();
        int m = min(cnt, 512);
        if (threadIdx.x == 0) {             // tiny insertion sort ascending (m ~ 1-3)
            for (int i = 1; i < m; i++) {
                int v = list[i]; int k = i - 1;
                while (k >= 0 && list[k] > v) { list[k + 1] = list[k]; k--; }
                list[k + 1] = v;
            }
        }
        __syncthreads();
        const float* regp = (l == 0) ? r0 : ((l == 1) ? r1 : r2);
        const float* ancp = (l == 0) ? a0 : ((l == 1) ? a1 : a2);
        for (int i = threadIdx.x; i < jt; i += blockDim.x) {
            int o = b * CAND_TOT + CB[l] + cgt + i;
            if (i < m) {
                int j = list[i];
                float4 rg = ((const float4*)regp)[(size_t)b * n + j];
                float4 an = ((const float4*)ancp)[(size_t)b * n + j];
                unsigned int meta = ((unsigned int)g_cls[b * NTOT + LO[l] + j] << 24)
                                  | ((unsigned int)l << 16) | (unsigned int)j;
                emit_cand(o, sc[j], meta, decode_box(rg, an));
            } else {
                emit_cand(o, NEGV, (7u << 16) | (unsigned int)i, make_float4(0.f, 0.f, 0.f, 0.f));
            }
        }
    }
}

// ---------------- Kernel D: sorted-tranche greedy NMS (smem keys, parallel select) ----------------
#define TR 512
struct SmemNMS {
    float4        sbox[TR];              // sorted boxes
    float4        abox[MAXDET];          // accepted boxes
    union {
        struct {
            unsigned long long tk[TR];   // tranche keys (gather order)
            int                tc[TR];   // tranche candidate slots
        } ph1;
        unsigned int row[TR][16];        // row[i] bit j: "i suppresses j" (sorted idx)
    } u;
    unsigned long long keys[CAND_TOT];   // all candidate keys (loaded once)
    unsigned long long prefix;
    unsigned long long Tlow;
    float         sscore[TR];
    float         aarea[MAXDET];
    unsigned int  hist[256];
    unsigned int  wsum[16];
    unsigned int  aw[16];
    unsigned char scls[TR];
    int krem, tcnt, na, processed;
};

__device__ __forceinline__ int supp_test(float4 A, float aA, float4 B, float aB) {
    float tlx = fmaxf(A.x, B.x), tly = fmaxf(A.y, B.y);
    float brx = fminf(A.z, B.z), bry = fminf(A.w, B.w);
    float w = fmaxf(brx - tlx, 0.f), h = fmaxf(bry - tly, 0.f);
    float inter = w * h;
    // exact integer equivalence of inter/max(union,1e-4) >= 0.5 (inter>0 guards clamp path)
    return (inter > 0.f) && (3.0f * inter >= aA + aB);
}

__global__ __launch_bounds__(TR, 1) void nms_kernel(float* __restrict__ out) {
    extern __shared__ __align__(16) unsigned char smem_raw[];
    SmemNMS& sm = *reinterpret_cast<SmemNMS*>(smem_raw);
    int b = blockIdx.x;
    int t = threadIdx.x;
    int lane = t & 31, warp = t >> 5;

    float* outS = out + b * MAXDET;
    float* outC = out + BATCH * MAXDET + b * MAXDET;
    float* outB = out + 2 * BATCH * MAXDET + (size_t)b * MAXDET * 4;

    // load all keys to smem once
    for (int i = t; i < CAND_TOT; i += TR) sm.keys[i] = g_ckey[b * CAND_TOT + i];
    if (t == 0) { sm.na = 0; sm.processed = 0; sm.Tlow = 0xFFFFFFFFFFFFFFFFull; }
    __syncthreads();

    for (int tranche = 0; tranche < (CAND_TOT + TR - 1) / TR; tranche++) {
        if (sm.na >= MAXDET || sm.processed >= CAND_TOT) break;   // uniform (post-barrier)
        int rem = CAND_TOT - sm.processed;
        unsigned long long Thi = sm.Tlow;
        unsigned long long T = 0;

        if (rem > TR) {
            // radix-select the TR-th largest key among {key < Thi} (keys unique, 56 bits)
            if (t == 0) { sm.prefix = 0; sm.krem = TR; }
            __syncthreads();
            for (int round = 0; round < 7; round++) {
                int shift = 48 - 8 * round;
                unsigned long long pref = sm.prefix;
                int krem = sm.krem;
                if (t < 256) sm.hist[t] = 0;
                __syncthreads();
                unsigned long long hm = (round == 0) ? 0ull : (0xFFFFFFFFFFFFFFFFull << (shift + 8));
                for (int i = t; i < CAND_TOT; i += TR) {
                    unsigned long long kk = sm.keys[i];
                    if (kk < Thi && (kk & hm) == pref) {
                        unsigned int bin = (unsigned int)(kk >> shift) & 255u;
                        unsigned int act = __activemask();
                        unsigned int mm = __match_any_sync(act, bin);
                        int leader = __ffs(mm) - 1;
                        if (lane == leader) atomicAdd(&sm.hist[bin], __popc(mm));
                    }
                }
                __syncthreads();
                // parallel suffix scan over 256 bins (warps 0..7 hold them; others idle-safe)
                unsigned int val = (t < 256) ? sm.hist[t] : 0u;
                unsigned int x = val;
#pragma unroll
                for (int off = 1; off < 32; off <<= 1) {
                    unsigned int y = __shfl_down_sync(0xFFFFFFFFu, x, off);
                    if (lane + off < 32) x += y;
                }
                if (lane == 0 && warp < 8) sm.wsum[warp] = x;
                __syncthreads();
                if (t < 256) {
                    unsigned int hi = 0;
                    for (int w2 = warp + 1; w2 < 8; w2++) hi += sm.wsum[w2];
                    unsigned int suf_incl = x + hi;
                    unsigned int suf_excl = suf_incl - val;
                    if (suf_excl < (unsigned int)krem && suf_incl >= (unsigned int)krem) {
                        sm.prefix = pref | ((unsigned long long)t << shift);
                        sm.krem = krem - (int)suf_excl;
                    }
                }
                __syncthreads();
            }
            T = sm.prefix;   // exact TR-th largest key below Thi
        }

        // gather tranche: keys in [T, Thi)
        if (t == 0) sm.tcnt = 0;
        __syncthreads();
        for (int i = t; i < CAND_TOT; i += TR) {
            unsigned long long kk = sm.keys[i];
            if (kk >= T && kk < Thi) {
                int p = atomicAdd(&sm.tcnt, 1);
                if (p < TR) { sm.u.ph1.tk[p] = kk; sm.u.ph1.tc[p] = i; }
            }
        }
        __syncthreads();
        int kc = min(sm.tcnt, TR);

        // rank within tranche (descending, unique keys -> exact permutation)
        int r = -1; float4 mybox; float mysc = 0.f; unsigned int mycls = 0;
        if (t < kc) {
            unsigned long long myk = sm.u.ph1.tk[t];
            int myc = sm.u.ph1.tc[t];
            int rr = 0;
            for (int j2 = 0; j2 < kc; j2++) rr += (sm.u.ph1.tk[j2] > myk) ? 1 : 0;
            r = rr;
            mybox = g_cbox[b * CAND_TOT + myc];
            mysc  = g_cscore[b * CAND_TOT + myc];
            mycls = g_cmeta[b * CAND_TOT + myc] >> 24;
        }
        __syncthreads();   // tk/tc reads done before union overwritten
        if (t < kc) {
            sm.sbox[r] = mybox;
            sm.sscore[r] = mysc;
            sm.scls[r] = (unsigned char)mycls;
        }
        if (t == 0) { sm.processed += kc; sm.Tlow = (rem > TR) ? T : 0ull; }
        __syncthreads();

        if (!(sm.sscore[0] > MIN_SC)) break;   // all remaining invalid (sorted desc) — uniform

        int na0 = sm.na;
        float4 bx; float ar = 0.f;
        int dead = 1;
        if (t < kc) {
            bx = sm.sbox[t];
            ar = (bx.z - bx.x) * (bx.w - bx.y);
            dead = !(sm.sscore[t] > MIN_SC);
            if (!dead) {
                for (int a2 = 0; a2 < na0; a2++)
                    if (supp_test(bx, ar, sm.abox[a2], sm.aarea[a2])) { dead = 1; break; }
            }
        }
        unsigned int rowp[16];
#pragma unroll
        for (int w = 0; w < 16; w++) rowp[w] = 0;
        if (!dead) {
            for (int j2 = t + 1; j2 < kc; j2++) {
                float4 bj = sm.sbox[j2];
                float aj = (bj.z - bj.x) * (bj.w - bj.y);
                if (supp_test(bx, ar, bj, aj)) rowp[j2 >> 5] |= (1u << (j2 & 31));
            }
        }
#pragma unroll
        for (int w = 0; w < 16; w++) sm.u.row[t][w] = rowp[w];
        unsigned int bal = __ballot_sync(0xFFFFFFFFu, !dead);
        if (lane == 0) sm.aw[warp] = bal;
        __syncthreads();

        // resolve: warp 0, lane w owns alive word w
        if (warp == 0) {
            unsigned int aw = (lane < 16) ? sm.aw[lane] : 0u;
            int na = sm.na;
            while (na < MAXDET) {
                unsigned int anyb = __ballot_sync(0xFFFFFFFFu, aw != 0u) & 0xFFFFu;
                if (!anyb) break;
                int w = __ffs(anyb) - 1;
                unsigned int word = __shfl_sync(0xFFFFFFFFu, aw, w);
                int bit = __ffs(word) - 1;
                int pos = w * 32 + bit;
                if (lane == 0) {
                    float4 bb = sm.sbox[pos];
                    outS[na] = sm.sscore[pos];
                    outC[na] = (float)sm.scls[pos];
                    ((float4*)outB)[na] = bb;
                    sm.abox[na] = bb;
                    sm.aarea[na] = (bb.z - bb.x) * (bb.w - bb.y);
                }
                if (lane < 16) aw &= ~sm.u.row[pos][lane];
                if (lane == w) aw &= ~(1u << bit);
                na++;
            }
            if (lane == 0) sm.na = na;
        }
        __syncthreads();
    }

    __syncthreads();
    int na = sm.na;
    for (int d = na + t; d < MAXDET; d += TR) {
        outS[d] = -1.0f;
        outC[d] = -1.0f;
        ((float4*)outB)[d] = make_float4(-1.f, -1.f, -1.f, -1.f);
    }
}

// ---------------- launch ----------------
extern "C" void kernel_launch(void* const* d_in, const int* in_sizes, int n_in,
                              void* d_out, int out_size) {
    (void)n_in; (void)out_size;

    // Autodetect input ordering (interleaved dict order vs grouped signature order)
    int interleaved = (in_sizes[1] == BATCH * N0 * 4) ? 1 : 0;
    const float* CLS[5]; const float* REG[5]; const float* ANC[5];
    for (int l = 0; l < 5; l++) {
        if (interleaved) {
            CLS[l] = (const float*)d_in[3 * l];
            REG[l] = (const float*)d_in[3 * l + 1];
            ANC[l] = (const float*)d_in[3 * l + 2];
        } else {
            CLS[l] = (const float*)d_in[l];
            REG[l] = (const float*)d_in[5 + l];
            ANC[l] = (const float*)d_in[10 + l];
        }
    }

    // warp-per-anchor: exact grid, no partial warps
    int sc_blocks = (BATCH * NTOT * 32) / 256;   // 613800*32/256 = 76725 exactly
    score_kernel<<<sc_blocks, 256>>>(CLS[0], CLS[1], CLS[2], CLS[3], CLS[4]);
    topk_thresh_kernel<<<24, 256>>>();
    compact_fixup_kernel<<<NBC + 24, 256>>>(REG[0], REG[1], REG[2], REG[3], REG[4],
                                            ANC[0], ANC[1], ANC[2], ANC[3], ANC[4]);
    cudaFuncSetAttribute(nms_kernel, cudaFuncAttributeMaxDynamicSharedMemorySize,
                         (int)sizeof(SmemNMS));
    nms_kernel<<<BATCH, TR, sizeof(SmemNMS)>>>((float*)d_out);
}